// round 11
// baseline (speedup 1.0000x reference)
#include <cuda_runtime.h>
#include <cuda_fp16.h>
#include <math.h>
#include <stdint.h>

// Problem constants
#define BB 8
#define SS 2048
#define DD 1024

// Tiles (fp16): 256x256 output per CTA, two M=128 atoms; BK=64 (=128B row)
#define BM 256
#define BN 256
#define BK 64

// tcgen05 only exists in the arch-specific (sm_103a) compilation pass.
#if defined(__CUDA_ARCH_FEAT_SM103_ALL) || defined(__CUDA_ARCH_FEAT_SM100_ALL) || \
    (defined(__CUDA_ARCH_SPECIFIC__) && (__CUDA_ARCH__ >= 1000))
#define HAS_TCGEN05 1
#else
#define HAS_TCGEN05 0
#endif

// Scratch (allocation-free rule: __device__ globals), all fp16 operands
__device__ __half g_XH[BB * SS * DD];         // input fp16
__device__ __half g_CH[BB * SS * DD];         // context fp16
__device__ __half g_WTH[4][DD * DD];          // WqT,WkT,WvT,WoT fp16
__device__ __half g_QH[BB * SS * DD];
__device__ __half g_KH[BB * SS * DD];
__device__ __half g_VTH[BB * SS * DD];        // V^T per batch [B, D, S] (written by V GEMM)
__device__ __half g_WH[(long long)BB * SS * SS];  // softmax weights fp16 copy
__device__ __half g_CTXH[BB * SS * DD];

// ---------------------------------------------------------------------------
// PTX helpers
// ---------------------------------------------------------------------------
__device__ __forceinline__ uint32_t smem_u32(const void* p) {
    uint32_t a;
    asm("{ .reg .u64 t; cvta.to.shared.u64 t, %1; cvt.u32.u64 %0, t; }" : "=r"(a) : "l"(p));
    return a;
}

#if HAS_TCGEN05
__device__ __forceinline__ uint32_t elect_one() {
    uint32_t pred;
    asm volatile("{\n\t.reg .pred p;\n\telect.sync _|p, 0xFFFFFFFF;\n\tselp.b32 %0, 1, 0, p;\n\t}" : "=r"(pred));
    return pred;
}
#define MBAR_INIT(addr, cnt) \
    asm volatile("mbarrier.init.shared.b64 [%0], %1;" :: "r"(addr), "r"(cnt) : "memory")
#define MBAR_WAIT(addr, par) do {                                              \
    uint32_t _m = (addr), _p = (par), _d;                                      \
    asm volatile("{\n\t.reg .pred p;\n\t"                                      \
        "mbarrier.try_wait.parity.acquire.cta.shared::cta.b64 p, [%1], %2;\n\t"\
        "selp.b32 %0, 1, 0, p;\n\t}" : "=r"(_d) : "r"(_m), "r"(_p) : "memory");\
    if (!_d) {                                                                 \
        asm volatile("{\n\t.reg .pred P1;\n\t"                                 \
        "W_%=:\n\t"                                                            \
        "mbarrier.try_wait.parity.acquire.cta.shared::cta.b64 P1, [%0], %1, 0x989680;\n\t" \
        "@P1 bra.uni D_%=;\n\tbra.uni W_%=;\n\tD_%=:\n\t}"                     \
        :: "r"(_m), "r"(_p) : "memory");                                       \
    }                                                                          \
} while (0)

#define TCG_ALLOC(smem_addr, n) \
    asm volatile("tcgen05.alloc.cta_group::1.sync.aligned.shared::cta.b32 [%0], %1;" :: "r"(smem_addr), "r"(n) : "memory")
#define TCG_RELINQ() \
    asm volatile("tcgen05.relinquish_alloc_permit.cta_group::1.sync.aligned;")
#define TCG_DEALLOC(tmem, n) \
    asm volatile("tcgen05.dealloc.cta_group::1.sync.aligned.b32 %0, %1;" :: "r"(tmem), "r"(n))
#define TCG_COMMIT(mbar) \
    asm volatile("tcgen05.commit.cta_group::1.mbarrier::arrive::one.shared::cluster.b64 [%0];" :: "r"(mbar) : "memory")
#define TCG_FENCE_BEFORE() asm volatile("tcgen05.fence::before_thread_sync;" ::: "memory")
#define TCG_FENCE_AFTER()  asm volatile("tcgen05.fence::after_thread_sync;" ::: "memory")
#define TCG_WAIT_LD()      asm volatile("tcgen05.wait::ld.sync.aligned;" ::: "memory")
#define FENCE_ASYNC_SHARED() asm volatile("fence.proxy.async.shared::cta;" ::: "memory")

// 16B async copy (LDGSTS): no register staging, cheap issue.
__device__ __forceinline__ void cp16(uint32_t dst, const void* src) {
    asm volatile("cp.async.cg.shared.global [%0], [%1], 16;" :: "r"(dst), "l"(src) : "memory");
}
#define CP_COMMIT() asm volatile("cp.async.commit_group;" ::: "memory")
#define CP_WAIT1()  asm volatile("cp.async.wait_group 1;" ::: "memory")
#define CP_WAIT0()  asm volatile("cp.async.wait_group 0;" ::: "memory")

#define TCG_LD_X32(r, tmem)                                                    \
    asm volatile("tcgen05.ld.sync.aligned.32x32b.x32.b32 "                     \
        "{%0, %1, %2, %3, %4, %5, %6, %7, %8, %9, %10, %11, %12, %13, %14, %15, " \
        " %16, %17, %18, %19, %20, %21, %22, %23, %24, %25, %26, %27, %28, %29, %30, %31}, [%32];" \
        : "=r"((r)[0]),  "=r"((r)[1]),  "=r"((r)[2]),  "=r"((r)[3]),           \
          "=r"((r)[4]),  "=r"((r)[5]),  "=r"((r)[6]),  "=r"((r)[7]),           \
          "=r"((r)[8]),  "=r"((r)[9]),  "=r"((r)[10]), "=r"((r)[11]),          \
          "=r"((r)[12]), "=r"((r)[13]), "=r"((r)[14]), "=r"((r)[15]),          \
          "=r"((r)[16]), "=r"((r)[17]), "=r"((r)[18]), "=r"((r)[19]),          \
          "=r"((r)[20]), "=r"((r)[21]), "=r"((r)[22]), "=r"((r)[23]),          \
          "=r"((r)[24]), "=r"((r)[25]), "=r"((r)[26]), "=r"((r)[27]),          \
          "=r"((r)[28]), "=r"((r)[29]), "=r"((r)[30]), "=r"((r)[31])           \
        : "r"(tmem))

// SW128 K-major SMEM descriptor (layout 2, version 1, LBO=1, SBO=64)
__device__ __forceinline__ uint64_t make_desc(uint32_t addr) {
    const uint64_t base = (uint64_t(2) << 61) | (uint64_t(1) << 46)
                        | (uint64_t(64) << 32) | (uint64_t(1) << 16);
    return base | ((uint64_t)(addr >> 4) & 0x3FFF);
}

// idesc kind::f16, fp16 inputs, fp32 accum; M=128 per atom, N=256
#define IDESC_F16 ((1u << 4) | ((BN / 8) << 17) | ((128 / 16) << 24))

__device__ __forceinline__ void mma_f16_ss(uint32_t d_tmem, uint64_t a_desc,
                                           uint64_t b_desc, uint32_t enable) {
    asm volatile(
        "{\n\t.reg .pred p;\n\t"
        "setp.ne.u32 p, %4, 0;\n\t"
        "tcgen05.mma.cta_group::1.kind::f16 [%0], %1, %2, %3, {%5, %5, %5, %5}, p;\n\t}"
        :: "r"(d_tmem), "l"(a_desc), "l"(b_desc), "r"(IDESC_F16),
           "r"(enable), "r"(0u)
        : "memory");
}
#endif // HAS_TCGEN05

__device__ __forceinline__ uint32_t swz(uint32_t off) {   // SW128 swizzle
    return off ^ ((off >> 3) & 0x70);
}

// SMEM layout (dynamic): [0]=tmem ptr, [16],[24]=mbar0/1, tiles 1024-aligned
// A tile = 256 rows x 128B = 32KB; B tile = 256 rows x 128B = 32KB; x2 stages
#define SM_TMEMPTR 0
#define SM_MBAR0   16
#define SM_MBAR1   24
#define SM_A0      1024
#define SM_A1      (SM_A0 + BM * 128)
#define SM_B0      (SM_A1 + BM * 128)
#define SM_B1      (SM_B0 + BN * 128)
#define SM_TOTAL   (SM_B1 + BN * 128)            // 1024 + 128KB = 132096

// ---------------------------------------------------------------------------
// fp16 NT GEMM on tcgen05:  C[m][n] = alpha * sum_k A[m][k] * B[n][k]
// 256x256 tile per CTA: two M=128 atoms into TMEM halves (cols 0 / 256).
// A: [M,K] fp16 rm (rows by*256), B: [N,K] fp16 rm (rows bx*256).
// outMode: 0 = fp32 C[M,ldc]; 1 = fp16 C[M,ldc];
//          2 = fp16 TRANSPOSED per-batch: C[b][n][s] with mGlobal=b*SS+s.
// K multiple of 64. Mainloop: cp.async prefetch-ahead, 2-stage double buffer.
// ---------------------------------------------------------------------------
__global__ void __launch_bounds__(256)
gemm_nt_f16(const __half* __restrict__ A, const __half* __restrict__ B,
            void* __restrict__ Cv, int K, int ldc,
            long long sA, long long sB, long long sC, float alpha, int outMode)
{
    const int tid = threadIdx.x;

    A += (long long)blockIdx.z * sA + (long long)blockIdx.y * BM * K;
    B += (long long)blockIdx.z * sB + (long long)blockIdx.x * BN * K;
    const long long cOff = (long long)blockIdx.z * sC
                         + (long long)blockIdx.y * BM * ldc
                         + (long long)blockIdx.x * BN;

#if HAS_TCGEN05
    extern __shared__ char smem[];
    const uint32_t sbase = smem_u32(smem);
    const int wid = tid >> 5;
    const int lid = tid & 31;

    if (wid == 0) {
        TCG_ALLOC(sbase + SM_TMEMPTR, 512);
        TCG_RELINQ();
    }
    if (tid == 0) {
        MBAR_INIT(sbase + SM_MBAR0, 1);
        MBAR_INIT(sbase + SM_MBAR1, 1);
    }
    __syncthreads();
    uint32_t tmem;
    asm volatile("ld.shared.b32 %0, [%1];" : "=r"(tmem) : "r"(sbase + SM_TMEMPTR));

    const int KT = K / BK;
    const int lrow  = tid >> 3;              // 0..31
    const int lcolB = (tid & 7) * 16;        // byte offset in row
    const int lcolE = (tid & 7) * 8;         // fp16 element offset

    auto fill = [&](int j) {
        const int buf = j & 1;
        const uint32_t aBase = sbase + (buf ? SM_A1 : SM_A0);
        const uint32_t bBase = sbase + (buf ? SM_B1 : SM_B0);
        const long long k0 = (long long)j * BK;
        #pragma unroll
        for (int p = 0; p < BM / 32; p++) {  // 8 passes, 256 A rows
            const int r = lrow + p * 32;
            cp16(aBase + swz((uint32_t)(r * 128 + lcolB)),
                 A + (long long)r * K + k0 + lcolE);
        }
        #pragma unroll
        for (int p = 0; p < BN / 32; p++) {  // 8 passes, 256 B rows
            const int r = lrow + p * 32;
            cp16(bBase + swz((uint32_t)(r * 128 + lcolB)),
                 B + (long long)r * K + k0 + lcolE);
        }
        CP_COMMIT();
    };

    fill(0);                                  // prologue prefetch

    for (int ic = 0; ic < KT; ic++) {
        const int buf = ic & 1;

        if (ic + 1 < KT) {
            const int j = ic + 1;
            const int use = j >> 1;
            if (use > 0) {
                const uint32_t m = sbase + ((j & 1) ? SM_MBAR1 : SM_MBAR0);
                MBAR_WAIT(m, (use - 1) & 1);
            }
            fill(j);
            CP_WAIT1();
        } else {
            CP_WAIT0();
        }
        FENCE_ASYNC_SHARED();
        __syncthreads();

        if (wid == 0) {
            if (elect_one()) {
                const uint32_t aBase = sbase + (buf ? SM_A1 : SM_A0);
                const uint32_t bBase = sbase + (buf ? SM_B1 : SM_B0);
                const uint64_t ad0 = make_desc(aBase);                 // rows 0..127
                const uint64_t ad1 = make_desc(aBase + 128 * 128);     // rows 128..255
                const uint64_t bd  = make_desc(bBase);
                #pragma unroll
                for (int s = 0; s < 4; s++) {   // 4 x K=16 fp16 steps
                    const uint32_t en = (ic > 0 || s > 0) ? 1u : 0u;
                    mma_f16_ss(tmem,       ad0 + s * 2, bd + s * 2, en);
                    mma_f16_ss(tmem + 256, ad1 + s * 2, bd + s * 2, en);
                }
                TCG_COMMIT(sbase + (buf ? SM_MBAR1 : SM_MBAR0));
            }
        }
    }

    {
        const int lastBuf = (KT - 1) & 1;
        const int cnt = (KT + 1) >> 1;
        const uint32_t mbar = sbase + (lastBuf ? SM_MBAR1 : SM_MBAR0);
        MBAR_WAIT(mbar, (cnt - 1) & 1);
    }
    TCG_FENCE_AFTER();

    // Epilogue: warp w drains TMEM half (w>>2), lanes (w&3)*32+lid.
    // Global row m = (w>>2)*128 + (w&3)*32 + lid; 256 cols per row (8 x LD_X32).
    {
        const int half = wid >> 2;
        const int m = half * 128 + (wid & 3) * 32 + lid;
        const uint32_t tbase_col = tmem + half * 256;
        // mode-2 precompute: global row -> (batch, s)
        const long long mG = (long long)blockIdx.y * BM + m;
        const long long b2 = mG >> 11;            // /SS
        const long long s2 = mG & (SS - 1);
        __half* vtbase = (__half*)Cv + b2 * ((long long)DD * SS) + s2
                       + (long long)(blockIdx.x * BN) * SS;
        #pragma unroll
        for (int j = 0; j < 8; j++) {
            uint32_t r[32];
            TCG_LD_X32(r, tbase_col + j * 32);
            TCG_WAIT_LD();
            float f[32];
            #pragma unroll
            for (int c = 0; c < 32; c++) f[c] = __uint_as_float(r[c]) * alpha;
            if (outMode == 0) {
                float* crow = (float*)Cv + cOff + (long long)m * ldc + j * 32;
                #pragma unroll
                for (int c = 0; c < 8; c++)
                    *reinterpret_cast<float4*>(crow + c * 4) =
                        *reinterpret_cast<float4*>(&f[c * 4]);
            } else if (outMode == 1) {
                __half* crow = (__half*)Cv + cOff + (long long)m * ldc + j * 32;
                #pragma unroll
                for (int c = 0; c < 4; c++) {
                    __half2 p0 = __floats2half2_rn(f[c*8+0], f[c*8+1]);
                    __half2 p1 = __floats2half2_rn(f[c*8+2], f[c*8+3]);
                    __half2 p2 = __floats2half2_rn(f[c*8+4], f[c*8+5]);
                    __half2 p3 = __floats2half2_rn(f[c*8+6], f[c*8+7]);
                    uint4 v = make_uint4(*(uint32_t*)&p0, *(uint32_t*)&p1,
                                         *(uint32_t*)&p2, *(uint32_t*)&p3);
                    *reinterpret_cast<uint4*>(crow + c * 8) = v;
                }
            } else {
                // Transposed fp16: element (m, n) -> C[b][n][s].
                #pragma unroll
                for (int c = 0; c < 32; c++)
                    vtbase[(long long)(j * 32 + c) * SS] = __float2half(f[c]);
            }
        }
    }
    TCG_FENCE_BEFORE();
    __syncthreads();
    if (wid == 0) TCG_DEALLOC(tmem, 512);

#else
    // Baseline-pass fallback (never selected at runtime on sm_103a).
    for (int half = 0; half < 2; half++) {
        const int trow = half * 128 + (tid >> 4) * 8;
        const int tcol = (tid & 15) * 16;
        float acc[8][16];
        #pragma unroll
        for (int i = 0; i < 8; i++)
            #pragma unroll
            for (int j = 0; j < 16; j++) acc[i][j] = 0.f;
        for (int k = 0; k < K; k++) {
            float ar[8], br[16];
            #pragma unroll
            for (int i = 0; i < 8; i++) ar[i] = __half2float(A[(long long)(trow + i) * K + k]);
            #pragma unroll
            for (int j = 0; j < 16; j++) br[j] = __half2float(B[(long long)(tcol + j) * K + k]);
            #pragma unroll
            for (int i = 0; i < 8; i++)
                #pragma unroll
                for (int j = 0; j < 16; j++)
                    acc[i][j] = fmaf(ar[i], br[j], acc[i][j]);
        }
        #pragma unroll
        for (int i = 0; i < 8; i++)
            #pragma unroll
            for (int j = 0; j < 16; j++) {
                const float val = acc[i][j] * alpha;
                if (outMode == 2) {
                    const long long mG = (long long)blockIdx.y * BM + trow + i;
                    const long long b2 = mG >> 11, s2 = mG & (SS - 1);
                    const long long n = blockIdx.x * BN + tcol + j;
                    ((__half*)Cv)[b2 * ((long long)DD * SS) + n * SS + s2] = __float2half(val);
                } else {
                    const long long idx = cOff + (long long)(trow + i) * ldc + tcol + j;
                    if (outMode == 1) ((__half*)Cv)[idx] = __float2half(val);
                    else              ((float*)Cv)[idx] = val;
                }
            }
    }
#endif
}

// ---------------------------------------------------------------------------
// Elementwise fp32 -> fp16 convert
// ---------------------------------------------------------------------------
__global__ void __launch_bounds__(256)
cvt_f32_f16(const float* __restrict__ in, __half* __restrict__ out, long long n)
{
    const long long i = ((long long)blockIdx.x * 256 + threadIdx.x) * 4;
    if (i + 3 < n) {
        float4 v = *reinterpret_cast<const float4*>(in + i);
        __half2 a = __floats2half2_rn(v.x, v.y);
        __half2 b = __floats2half2_rn(v.z, v.w);
        uint32_t pa = *reinterpret_cast<uint32_t*>(&a);
        uint32_t pb = *reinterpret_cast<uint32_t*>(&b);
        *reinterpret_cast<uint2*>(out + i) = make_uint2(pa, pb);
    }
}

// ---------------------------------------------------------------------------
// Transpose fp32 -> fp16: out[c][r] = (half) in[r][c]  (weights only)
// ---------------------------------------------------------------------------
__global__ void __launch_bounds__(256)
transpose_f32_to_f16(const float* __restrict__ in, __half* __restrict__ out,
                     int R, int C)
{
    __shared__ float t[32][33];
    const int c0 = blockIdx.x * 32, r0 = blockIdx.y * 32;
    #pragma unroll
    for (int i = threadIdx.y; i < 32; i += 8)
        t[i][threadIdx.x] = in[(long long)(r0 + i) * C + c0 + threadIdx.x];
    __syncthreads();
    #pragma unroll
    for (int i = threadIdx.y; i < 32; i += 8)
        out[(long long)(c0 + i) * R + r0 + threadIdx.x] = __float2half(t[threadIdx.x][i]);
}

// ---------------------------------------------------------------------------
// Row softmax in place (fp32) + fp16 copy. One block per row, 256 threads.
// Vectorized: thread t owns cols [8t, 8t+8) as 2x float4.
// ---------------------------------------------------------------------------
__inline__ __device__ float warpMax(float v) {
    #pragma unroll
    for (int o = 16; o > 0; o >>= 1) v = fmaxf(v, __shfl_xor_sync(0xffffffffu, v, o));
    return v;
}
__inline__ __device__ float warpSum(float v) {
    #pragma unroll
    for (int o = 16; o > 0; o >>= 1) v += __shfl_xor_sync(0xffffffffu, v, o);
    return v;
}

__global__ void __launch_bounds__(256)
softmax_rows(float* __restrict__ W, __half* __restrict__ WH)
{
    float* row = W + (long long)blockIdx.x * SS;
    __half* hrow = WH + (long long)blockIdx.x * SS;
    const int tid = threadIdx.x;
    const int base = tid * 8;
    __shared__ float red[8];

    float4 v0 = *reinterpret_cast<const float4*>(row + base);
    float4 v1 = *reinterpret_cast<const float4*>(row + base + 4);
    float v[8] = { v0.x, v0.y, v0.z, v0.w, v1.x, v1.y, v1.z, v1.w };

    float m = v[0];
    #pragma unroll
    for (int i = 1; i < 8; i++) m = fmaxf(m, v[i]);
    m = warpMax(m);
    if ((tid & 31) == 0) red[tid >> 5] = m;
    __syncthreads();
    if (tid < 32) {
        float t = (tid < 8) ? red[tid] : -INFINITY;
        t = warpMax(t);
        if (tid == 0) red[0] = t;
    }
    __syncthreads();
    m = red[0];

    float s = 0.f;
    #pragma unroll
    for (int i = 0; i < 8; i++) {
        v[i] = __expf(v[i] - m);
        s += v[i];
    }
    s = warpSum(s);
    __syncthreads();
    if ((tid & 31) == 0) red[tid >> 5] = s;
    __syncthreads();
    if (tid < 32) {
        float t = (tid < 8) ? red[tid] : 0.f;
        t = warpSum(t);
        if (tid == 0) red[0] = t;
    }
    __syncthreads();
    const float inv = 1.0f / red[0];

    #pragma unroll
    for (int i = 0; i < 8; i++) v[i] *= inv;

    *reinterpret_cast<float4*>(row + base)     = make_float4(v[0], v[1], v[2], v[3]);
    *reinterpret_cast<float4*>(row + base + 4) = make_float4(v[4], v[5], v[6], v[7]);
    __half2 h0 = __floats2half2_rn(v[0], v[1]);
    __half2 h1 = __floats2half2_rn(v[2], v[3]);
    __half2 h2 = __floats2half2_rn(v[4], v[5]);
    __half2 h3 = __floats2half2_rn(v[6], v[7]);
    uint4 hv = make_uint4(*(uint32_t*)&h0, *(uint32_t*)&h1,
                          *(uint32_t*)&h2, *(uint32_t*)&h3);
    *reinterpret_cast<uint4*>(hrow + base) = hv;
}

// ---------------------------------------------------------------------------
// kernel_launch
// d_in: 0=input [B,S,D], 1=context [B,S,D], 2=Wq, 3=Wk, 4=Wv, 5=Wo ([D,D])
// d_out: output [B,S,D] then weights [B,S,S], fp32.
// ---------------------------------------------------------------------------
extern "C" void kernel_launch(void* const* d_in, const int* in_sizes, int n_in,
                              void* d_out, int out_size)
{
    const float* input   = (const float*)d_in[0];
    const float* context = (const float*)d_in[1];
    const float* Wq      = (const float*)d_in[2];
    const float* Wk      = (const float*)d_in[3];
    const float* Wv      = (const float*)d_in[4];
    const float* Wo      = (const float*)d_in[5];

    float* out     = (float*)d_out;                          // [B,S,D]
    float* weights = out + (long long)BB * SS * DD;          // [B,S,S]

    __half *xh, *ch, *wth, *qh, *kh, *vth, *wh, *ctxh;
    cudaGetSymbolAddress((void**)&xh,   g_XH);
    cudaGetSymbolAddress((void**)&ch,   g_CH);
    cudaGetSymbolAddress((void**)&wth,  g_WTH);
    cudaGetSymbolAddress((void**)&qh,   g_QH);
    cudaGetSymbolAddress((void**)&kh,   g_KH);
    cudaGetSymbolAddress((void**)&vth,  g_VTH);
    cudaGetSymbolAddress((void**)&wh,   g_WH);
    cudaGetSymbolAddress((void**)&ctxh, g_CTXH);
    __half* WqT = wth;
    __half* WkT = wth + 1 * DD * DD;
    __half* WvT = wth + 2 * DD * DD;
    __half* WoT = wth + 3 * DD * DD;

    cudaFuncSetAttribute(gemm_nt_f16,
                         cudaFuncAttributeMaxDynamicSharedMemorySize, SM_TOTAL);

    const dim3 blk(256);
    const dim3 tblk(32, 8);
    const long long SD  = (long long)SS * DD;
    const long long SSq = (long long)SS * SS;
    const long long NX  = (long long)BB * SS * DD;

    // 0) Convert inputs + transposed weights to fp16 (once per launch)
    cvt_f32_f16<<<(unsigned)((NX / 4 + 255) / 256), blk>>>(input,   xh, NX);
    cvt_f32_f16<<<(unsigned)((NX / 4 + 255) / 256), blk>>>(context, ch, NX);
    {
        dim3 g(DD / 32, DD / 32, 1);
        transpose_f32_to_f16<<<g, tblk>>>(Wq, WqT, DD, DD);
        transpose_f32_to_f16<<<g, tblk>>>(Wk, WkT, DD, DD);
        transpose_f32_to_f16<<<g, tblk>>>(Wv, WvT, DD, DD);
        transpose_f32_to_f16<<<g, tblk>>>(Wo, WoT, DD, DD);
    }

    // 1) Projections: Q,K fp16; V written TRANSPOSED directly (mode 2)
    {
        dim3 g(DD / BN, (BB * SS) / BM, 1);
        gemm_nt_f16<<<g, blk, SM_TOTAL>>>(xh, WqT, qh,  DD, DD, 0, 0, 0, 1.0f, 1);
        gemm_nt_f16<<<g, blk, SM_TOTAL>>>(ch, WkT, kh,  DD, DD, 0, 0, 0, 1.0f, 1);
        gemm_nt_f16<<<g, blk, SM_TOTAL>>>(ch, WvT, vth, DD, DD, 0, 0, 0, 1.0f, 2);
    }

    // 2) scores = Q @ K^T * (1/sqrt(D)) -> weights slice (fp32 out)
    {
        dim3 g(SS / BN, SS / BM, BB);
        gemm_nt_f16<<<g, blk, SM_TOTAL>>>(qh, kh, weights, DD, SS, SD, SD, SSq, 0.03125f, 0);
    }

    // 3) softmax in place (fp32) + fp16 copy
    softmax_rows<<<BB * SS, blk>>>(weights, wh);

    // 4) ctx = weights @ V == NT with V^T rows (fp16 out)
    {
        dim3 g(DD / BN, SS / BM, BB);
        gemm_nt_f16<<<g, blk, SM_TOTAL>>>(wh, vth, ctxh, SS, DD, SSq, SD, SD, 1.0f, 1);
    }

    // 5) output = ctx @ Wo == NT with Wo^T (fp32 out)
    {
        dim3 g(DD / BN, (BB * SS) / BM, 1);
        gemm_nt_f16<<<g, blk, SM_TOTAL>>>(ctxh, WoT, out, DD, DD, 0, 0, 0, 1.0f, 0);
    }
}

// round 12
// speedup vs baseline: 1.1504x; 1.1504x over previous
#include <cuda_runtime.h>
#include <cuda_fp16.h>
#include <math.h>
#include <stdint.h>

// Problem constants
#define BB 8
#define SS 2048
#define DD 1024

// Tiles (fp16): one SW128 row = 128 bytes = 64 fp16 K-elements
#define BM 128
#define BN 256
#define BK 64

// tcgen05 only exists in the arch-specific (sm_103a) compilation pass.
#if defined(__CUDA_ARCH_FEAT_SM103_ALL) || defined(__CUDA_ARCH_FEAT_SM100_ALL) || \
    (defined(__CUDA_ARCH_SPECIFIC__) && (__CUDA_ARCH__ >= 1000))
#define HAS_TCGEN05 1
#else
#define HAS_TCGEN05 0
#endif

// Scratch (allocation-free rule: __device__ globals), all fp16 operands
__device__ __half g_XH[BB * SS * DD];         // input fp16
__device__ __half g_CH[BB * SS * DD];         // context fp16
__device__ __half g_WTH[4][DD * DD];          // WqT,WkT,WvT,WoT fp16
__device__ __half g_QH[BB * SS * DD];
__device__ __half g_KH[BB * SS * DD];
__device__ __half g_VTH[BB * SS * DD];        // V^T per batch [B, D, S] (written by V GEMM)
__device__ __half g_WH[(long long)BB * SS * SS];  // softmax weights fp16 copy
__device__ __half g_CTXH[BB * SS * DD];

// ---------------------------------------------------------------------------
// PTX helpers
// ---------------------------------------------------------------------------
__device__ __forceinline__ uint32_t smem_u32(const void* p) {
    uint32_t a;
    asm("{ .reg .u64 t; cvta.to.shared.u64 t, %1; cvt.u32.u64 %0, t; }" : "=r"(a) : "l"(p));
    return a;
}

#if HAS_TCGEN05
__device__ __forceinline__ uint32_t elect_one() {
    uint32_t pred;
    asm volatile("{\n\t.reg .pred p;\n\telect.sync _|p, 0xFFFFFFFF;\n\tselp.b32 %0, 1, 0, p;\n\t}" : "=r"(pred));
    return pred;
}
#define MBAR_INIT(addr, cnt) \
    asm volatile("mbarrier.init.shared.b64 [%0], %1;" :: "r"(addr), "r"(cnt) : "memory")
#define MBAR_WAIT(addr, par) do {                                              \
    uint32_t _m = (addr), _p = (par), _d;                                      \
    asm volatile("{\n\t.reg .pred p;\n\t"                                      \
        "mbarrier.try_wait.parity.acquire.cta.shared::cta.b64 p, [%1], %2;\n\t"\
        "selp.b32 %0, 1, 0, p;\n\t}" : "=r"(_d) : "r"(_m), "r"(_p) : "memory");\
    if (!_d) {                                                                 \
        asm volatile("{\n\t.reg .pred P1;\n\t"                                 \
        "W_%=:\n\t"                                                            \
        "mbarrier.try_wait.parity.acquire.cta.shared::cta.b64 P1, [%0], %1, 0x989680;\n\t" \
        "@P1 bra.uni D_%=;\n\tbra.uni W_%=;\n\tD_%=:\n\t}"                     \
        :: "r"(_m), "r"(_p) : "memory");                                       \
    }                                                                          \
} while (0)

#define TCG_ALLOC(smem_addr, n) \
    asm volatile("tcgen05.alloc.cta_group::1.sync.aligned.shared::cta.b32 [%0], %1;" :: "r"(smem_addr), "r"(n) : "memory")
#define TCG_RELINQ() \
    asm volatile("tcgen05.relinquish_alloc_permit.cta_group::1.sync.aligned;")
#define TCG_DEALLOC(tmem, n) \
    asm volatile("tcgen05.dealloc.cta_group::1.sync.aligned.b32 %0, %1;" :: "r"(tmem), "r"(n))
#define TCG_COMMIT(mbar) \
    asm volatile("tcgen05.commit.cta_group::1.mbarrier::arrive::one.shared::cluster.b64 [%0];" :: "r"(mbar) : "memory")
#define TCG_FENCE_BEFORE() asm volatile("tcgen05.fence::before_thread_sync;" ::: "memory")
#define TCG_FENCE_AFTER()  asm volatile("tcgen05.fence::after_thread_sync;" ::: "memory")
#define TCG_WAIT_LD()      asm volatile("tcgen05.wait::ld.sync.aligned;" ::: "memory")
#define FENCE_ASYNC_SHARED() asm volatile("fence.proxy.async.shared::cta;" ::: "memory")

// 16B async copy (LDGSTS): no register staging, cheap issue.
__device__ __forceinline__ void cp16(uint32_t dst, const void* src) {
    asm volatile("cp.async.cg.shared.global [%0], [%1], 16;" :: "r"(dst), "l"(src) : "memory");
}
#define CP_COMMIT() asm volatile("cp.async.commit_group;" ::: "memory")
#define CP_WAIT1()  asm volatile("cp.async.wait_group 1;" ::: "memory")
#define CP_WAIT0()  asm volatile("cp.async.wait_group 0;" ::: "memory")

#define TCG_LD_X32(r, tmem)                                                    \
    asm volatile("tcgen05.ld.sync.aligned.32x32b.x32.b32 "                     \
        "{%0, %1, %2, %3, %4, %5, %6, %7, %8, %9, %10, %11, %12, %13, %14, %15, " \
        " %16, %17, %18, %19, %20, %21, %22, %23, %24, %25, %26, %27, %28, %29, %30, %31}, [%32];" \
        : "=r"((r)[0]),  "=r"((r)[1]),  "=r"((r)[2]),  "=r"((r)[3]),           \
          "=r"((r)[4]),  "=r"((r)[5]),  "=r"((r)[6]),  "=r"((r)[7]),           \
          "=r"((r)[8]),  "=r"((r)[9]),  "=r"((r)[10]), "=r"((r)[11]),          \
          "=r"((r)[12]), "=r"((r)[13]), "=r"((r)[14]), "=r"((r)[15]),          \
          "=r"((r)[16]), "=r"((r)[17]), "=r"((r)[18]), "=r"((r)[19]),          \
          "=r"((r)[20]), "=r"((r)[21]), "=r"((r)[22]), "=r"((r)[23]),          \
          "=r"((r)[24]), "=r"((r)[25]), "=r"((r)[26]), "=r"((r)[27]),          \
          "=r"((r)[28]), "=r"((r)[29]), "=r"((r)[30]), "=r"((r)[31])           \
        : "r"(tmem))

// SW128 K-major SMEM descriptor (layout 2, version 1, LBO=1, SBO=64)
__device__ __forceinline__ uint64_t make_desc(uint32_t addr) {
    const uint64_t base = (uint64_t(2) << 61) | (uint64_t(1) << 46)
                        | (uint64_t(64) << 32) | (uint64_t(1) << 16);
    return base | ((uint64_t)(addr >> 4) & 0x3FFF);
}

// idesc kind::f16, fp16 inputs, fp32 accum
#define IDESC_F16 ((1u << 4) | ((BN / 8) << 17) | ((BM / 16) << 24))

__device__ __forceinline__ void mma_f16_ss(uint32_t d_tmem, uint64_t a_desc,
                                           uint64_t b_desc, uint32_t enable) {
    asm volatile(
        "{\n\t.reg .pred p;\n\t"
        "setp.ne.u32 p, %4, 0;\n\t"
        "tcgen05.mma.cta_group::1.kind::f16 [%0], %1, %2, %3, {%5, %5, %5, %5}, p;\n\t}"
        :: "r"(d_tmem), "l"(a_desc), "l"(b_desc), "r"(IDESC_F16),
           "r"(enable), "r"(0u)
        : "memory");
}
#endif // HAS_TCGEN05

__device__ __forceinline__ uint32_t swz(uint32_t off) {   // SW128 swizzle
    return off ^ ((off >> 3) & 0x70);
}

// SMEM layout (dynamic): [0]=tmem ptr, [16],[24]=mbar0/1, tiles 1024-aligned
#define SM_TMEMPTR 0
#define SM_MBAR0   16
#define SM_MBAR1   24
#define SM_A0      1024
#define SM_A1      (SM_A0 + BM * 128)            // A tile = 16KB
#define SM_B0      (SM_A1 + BM * 128)
#define SM_B1      (SM_B0 + BN * 128)            // B tile = 32KB
#define SM_TOTAL   (SM_B1 + BN * 128)            // 99328

// ---------------------------------------------------------------------------
// fp16 NT GEMM on tcgen05:  C[m][n] = alpha * sum_k A[m][k] * B[n][k]
// A: [M,K] fp16 rm (rows by*128), B: [N,K] fp16 rm (rows bx*256).
// outMode: 0 = fp32 C[M,ldc]; 1 = fp16 C[M,ldc];
//          2 = fp16 TRANSPOSED per-batch: C[b][n][s] with mGlobal=b*SS+s.
// K multiple of 64. Mainloop: cp.async prefetch-ahead, 2-stage double buffer.
// ---------------------------------------------------------------------------
__global__ void __launch_bounds__(256)
gemm_nt_f16(const __half* __restrict__ A, const __half* __restrict__ B,
            void* __restrict__ Cv, int K, int ldc,
            long long sA, long long sB, long long sC, float alpha, int outMode)
{
    const int tid = threadIdx.x;

    A += (long long)blockIdx.z * sA + (long long)blockIdx.y * BM * K;
    B += (long long)blockIdx.z * sB + (long long)blockIdx.x * BN * K;
    const long long cOff = (long long)blockIdx.z * sC
                         + (long long)blockIdx.y * BM * ldc
                         + (long long)blockIdx.x * BN;

#if HAS_TCGEN05
    extern __shared__ char smem[];
    const uint32_t sbase = smem_u32(smem);
    const int wid = tid >> 5;
    const int lid = tid & 31;

    if (wid == 0) {
        TCG_ALLOC(sbase + SM_TMEMPTR, 256);
        TCG_RELINQ();
    }
    if (tid == 0) {
        MBAR_INIT(sbase + SM_MBAR0, 1);
        MBAR_INIT(sbase + SM_MBAR1, 1);
    }
    __syncthreads();
    uint32_t tmem;
    asm volatile("ld.shared.b32 %0, [%1];" : "=r"(tmem) : "r"(sbase + SM_TMEMPTR));

    const int KT = K / BK;
    const int lrow  = tid >> 3;
    const int lcolB = (tid & 7) * 16;        // byte offset in row
    const int lcolE = (tid & 7) * 8;         // fp16 element offset

    auto fill = [&](int j) {
        const int buf = j & 1;
        const uint32_t aBase = sbase + (buf ? SM_A1 : SM_A0);
        const uint32_t bBase = sbase + (buf ? SM_B1 : SM_B0);
        const long long k0 = (long long)j * BK;
        #pragma unroll
        for (int p = 0; p < BM / 32; p++) {
            const int r = lrow + p * 32;
            cp16(aBase + swz((uint32_t)(r * 128 + lcolB)),
                 A + (long long)r * K + k0 + lcolE);
        }
        #pragma unroll
        for (int p = 0; p < BN / 32; p++) {
            const int r = lrow + p * 32;
            cp16(bBase + swz((uint32_t)(r * 128 + lcolB)),
                 B + (long long)r * K + k0 + lcolE);
        }
        CP_COMMIT();
    };

    fill(0);                                  // prologue prefetch

    for (int ic = 0; ic < KT; ic++) {
        const int buf = ic & 1;

        if (ic + 1 < KT) {
            const int j = ic + 1;
            const int use = j >> 1;
            if (use > 0) {
                const uint32_t m = sbase + ((j & 1) ? SM_MBAR1 : SM_MBAR0);
                MBAR_WAIT(m, (use - 1) & 1);
            }
            fill(j);
            CP_WAIT1();
        } else {
            CP_WAIT0();
        }
        FENCE_ASYNC_SHARED();
        __syncthreads();

        if (wid == 0) {
            if (elect_one()) {
                const uint32_t aBase = sbase + (buf ? SM_A1 : SM_A0);
                const uint32_t bBase = sbase + (buf ? SM_B1 : SM_B0);
                const uint64_t ad = make_desc(aBase);
                const uint64_t bd = make_desc(bBase);
                #pragma unroll
                for (int s = 0; s < 4; s++) {
                    mma_f16_ss(tmem, ad + s * 2, bd + s * 2,
                               (ic > 0 || s > 0) ? 1u : 0u);
                }
                TCG_COMMIT(sbase + (buf ? SM_MBAR1 : SM_MBAR0));
            }
        }
    }

    {
        const int lastBuf = (KT - 1) & 1;
        const int cnt = (KT + 1) >> 1;
        const uint32_t mbar = sbase + (lastBuf ? SM_MBAR1 : SM_MBAR0);
        MBAR_WAIT(mbar, (cnt - 1) & 1);
    }
    TCG_FENCE_AFTER();

    // Epilogue: 8 warps; rows (wid&3)*32+lid, col half (wid>>2)*128.
    // Paired TMEM loads: issue 2 x LD_X32, wait once, store both.
    {
        const int m = (wid & 3) * 32 + lid;
        const int chalf = (wid >> 2) * 128;
        const long long mG = (long long)blockIdx.y * BM + m;
        const long long b2 = mG >> 11;            // /SS
        const long long s2 = mG & (SS - 1);
        __half* tbase = (__half*)Cv + b2 * ((long long)DD * SS) + s2
                      + (long long)(blockIdx.x * BN + chalf) * SS;
        #pragma unroll
        for (int jp = 0; jp < 2; jp++) {          // 2 pairs of 32-col groups
            uint32_t r0[32], r1[32];
            TCG_LD_X32(r0, tmem + chalf + (jp * 2 + 0) * 32);
            TCG_LD_X32(r1, tmem + chalf + (jp * 2 + 1) * 32);
            TCG_WAIT_LD();
            float f[64];
            #pragma unroll
            for (int c = 0; c < 32; c++) f[c]      = __uint_as_float(r0[c]) * alpha;
            #pragma unroll
            for (int c = 0; c < 32; c++) f[32 + c] = __uint_as_float(r1[c]) * alpha;
            if (outMode == 0) {
                float* crow = (float*)Cv + cOff + (long long)m * ldc + chalf + jp * 64;
                #pragma unroll
                for (int c = 0; c < 16; c++)
                    *reinterpret_cast<float4*>(crow + c * 4) =
                        *reinterpret_cast<float4*>(&f[c * 4]);
            } else if (outMode == 1) {
                __half* crow = (__half*)Cv + cOff + (long long)m * ldc + chalf + jp * 64;
                #pragma unroll
                for (int c = 0; c < 8; c++) {
                    __half2 p0 = __floats2half2_rn(f[c*8+0], f[c*8+1]);
                    __half2 p1 = __floats2half2_rn(f[c*8+2], f[c*8+3]);
                    __half2 p2 = __floats2half2_rn(f[c*8+4], f[c*8+5]);
                    __half2 p3 = __floats2half2_rn(f[c*8+6], f[c*8+7]);
                    uint4 v = make_uint4(*(uint32_t*)&p0, *(uint32_t*)&p1,
                                         *(uint32_t*)&p2, *(uint32_t*)&p3);
                    *reinterpret_cast<uint4*>(crow + c * 8) = v;
                }
            } else {
                // Transposed fp16: element (m, n) -> C[b][n][s].
                #pragma unroll
                for (int c = 0; c < 64; c++)
                    tbase[(long long)(jp * 64 + c) * SS] = __float2half(f[c]);
            }
        }
    }
    TCG_FENCE_BEFORE();
    __syncthreads();
    if (wid == 0) TCG_DEALLOC(tmem, 256);

#else
    // Baseline-pass fallback (never selected at runtime on sm_103a).
    const int trow = (tid >> 4) * 8;
    const int tcol = (tid & 15) * 16;
    float acc[8][16];
    #pragma unroll
    for (int i = 0; i < 8; i++)
        #pragma unroll
        for (int j = 0; j < 16; j++) acc[i][j] = 0.f;
    for (int k = 0; k < K; k++) {
        float ar[8], br[16];
        #pragma unroll
        for (int i = 0; i < 8; i++) ar[i] = __half2float(A[(long long)(trow + i) * K + k]);
        #pragma unroll
        for (int j = 0; j < 16; j++) br[j] = __half2float(B[(long long)(tcol + j) * K + k]);
        #pragma unroll
        for (int i = 0; i < 8; i++)
            #pragma unroll
            for (int j = 0; j < 16; j++)
                acc[i][j] = fmaf(ar[i], br[j], acc[i][j]);
    }
    #pragma unroll
    for (int i = 0; i < 8; i++)
        #pragma unroll
        for (int j = 0; j < 16; j++) {
            const float val = acc[i][j] * alpha;
            if (outMode == 2) {
                const long long mG = (long long)blockIdx.y * BM + trow + i;
                const long long b2 = mG >> 11, s2 = mG & (SS - 1);
                const long long n = blockIdx.x * BN + tcol + j;
                ((__half*)Cv)[b2 * ((long long)DD * SS) + n * SS + s2] = __float2half(val);
            } else {
                const long long idx = cOff + (long long)(trow + i) * ldc + tcol + j;
                if (outMode == 1) ((__half*)Cv)[idx] = __float2half(val);
                else              ((float*)Cv)[idx] = val;
            }
        }
#endif
}

// ---------------------------------------------------------------------------
// Fused dual convert fp32 -> fp16 (input + context in one launch)
// ---------------------------------------------------------------------------
__global__ void __launch_bounds__(256)
cvt2_f32_f16(const float* __restrict__ in0, __half* __restrict__ out0,
             const float* __restrict__ in1, __half* __restrict__ out1,
             long long n)
{
    const long long i = ((long long)blockIdx.x * 256 + threadIdx.x) * 4;
    if (i + 3 < n) {
        float4 v = *reinterpret_cast<const float4*>(in0 + i);
        __half2 a = __floats2half2_rn(v.x, v.y);
        __half2 b = __floats2half2_rn(v.z, v.w);
        *reinterpret_cast<uint2*>(out0 + i) =
            make_uint2(*(uint32_t*)&a, *(uint32_t*)&b);
        float4 w = *reinterpret_cast<const float4*>(in1 + i);
        __half2 c = __floats2half2_rn(w.x, w.y);
        __half2 d = __floats2half2_rn(w.z, w.w);
        *reinterpret_cast<uint2*>(out1 + i) =
            make_uint2(*(uint32_t*)&c, *(uint32_t*)&d);
    }
}

// ---------------------------------------------------------------------------
// Batched transpose fp32 -> fp16: out[z][c][r] = (half) in[z][r][c]
// z = blockIdx.z selects among 4 weight matrices (ptr array via params).
// ---------------------------------------------------------------------------
__global__ void __launch_bounds__(256)
transpose4_f32_to_f16(const float* __restrict__ w0, const float* __restrict__ w1,
                      const float* __restrict__ w2, const float* __restrict__ w3,
                      __half* __restrict__ outBase)
{
    __shared__ float t[32][33];
    const float* in = (blockIdx.z == 0) ? w0 : (blockIdx.z == 1) ? w1
                    : (blockIdx.z == 2) ? w2 : w3;
    __half* out = outBase + (long long)blockIdx.z * DD * DD;
    const int c0 = blockIdx.x * 32, r0 = blockIdx.y * 32;
    #pragma unroll
    for (int i = threadIdx.y; i < 32; i += 8)
        t[i][threadIdx.x] = in[(long long)(r0 + i) * DD + c0 + threadIdx.x];
    __syncthreads();
    #pragma unroll
    for (int i = threadIdx.y; i < 32; i += 8)
        out[(long long)(c0 + i) * DD + r0 + threadIdx.x] = __float2half(t[threadIdx.x][i]);
}

// ---------------------------------------------------------------------------
// Row softmax in place (fp32) + fp16 copy. One block per row, 256 threads.
// Vectorized: thread t owns cols [8t, 8t+8) as 2x float4.
// ---------------------------------------------------------------------------
__inline__ __device__ float warpMax(float v) {
    #pragma unroll
    for (int o = 16; o > 0; o >>= 1) v = fmaxf(v, __shfl_xor_sync(0xffffffffu, v, o));
    return v;
}
__inline__ __device__ float warpSum(float v) {
    #pragma unroll
    for (int o = 16; o > 0; o >>= 1) v += __shfl_xor_sync(0xffffffffu, v, o);
    return v;
}

__global__ void __launch_bounds__(256)
softmax_rows(float* __restrict__ W, __half* __restrict__ WH)
{
    float* row = W + (long long)blockIdx.x * SS;
    __half* hrow = WH + (long long)blockIdx.x * SS;
    const int tid = threadIdx.x;
    const int base = tid * 8;
    __shared__ float red[8];

    float4 v0 = *reinterpret_cast<const float4*>(row + base);
    float4 v1 = *reinterpret_cast<const float4*>(row + base + 4);
    float v[8] = { v0.x, v0.y, v0.z, v0.w, v1.x, v1.y, v1.z, v1.w };

    float m = v[0];
    #pragma unroll
    for (int i = 1; i < 8; i++) m = fmaxf(m, v[i]);
    m = warpMax(m);
    if ((tid & 31) == 0) red[tid >> 5] = m;
    __syncthreads();
    if (tid < 32) {
        float t = (tid < 8) ? red[tid] : -INFINITY;
        t = warpMax(t);
        if (tid == 0) red[0] = t;
    }
    __syncthreads();
    m = red[0];

    float s = 0.f;
    #pragma unroll
    for (int i = 0; i < 8; i++) {
        v[i] = __expf(v[i] - m);
        s += v[i];
    }
    s = warpSum(s);
    __syncthreads();
    if ((tid & 31) == 0) red[tid >> 5] = s;
    __syncthreads();
    if (tid < 32) {
        float t = (tid < 8) ? red[tid] : 0.f;
        t = warpSum(t);
        if (tid == 0) red[0] = t;
    }
    __syncthreads();
    const float inv = 1.0f / red[0];

    #pragma unroll
    for (int i = 0; i < 8; i++) v[i] *= inv;

    *reinterpret_cast<float4*>(row + base)     = make_float4(v[0], v[1], v[2], v[3]);
    *reinterpret_cast<float4*>(row + base + 4) = make_float4(v[4], v[5], v[6], v[7]);
    __half2 h0 = __floats2half2_rn(v[0], v[1]);
    __half2 h1 = __floats2half2_rn(v[2], v[3]);
    __half2 h2 = __floats2half2_rn(v[4], v[5]);
    __half2 h3 = __floats2half2_rn(v[6], v[7]);
    uint4 hv = make_uint4(*(uint32_t*)&h0, *(uint32_t*)&h1,
                          *(uint32_t*)&h2, *(uint32_t*)&h3);
    *reinterpret_cast<uint4*>(hrow + base) = hv;
}

// ---------------------------------------------------------------------------
// kernel_launch
// d_in: 0=input [B,S,D], 1=context [B,S,D], 2=Wq, 3=Wk, 4=Wv, 5=Wo ([D,D])
// d_out: output [B,S,D] then weights [B,S,S], fp32.
// ---------------------------------------------------------------------------
extern "C" void kernel_launch(void* const* d_in, const int* in_sizes, int n_in,
                              void* d_out, int out_size)
{
    const float* input   = (const float*)d_in[0];
    const float* context = (const float*)d_in[1];
    const float* Wq      = (const float*)d_in[2];
    const float* Wk      = (const float*)d_in[3];
    const float* Wv      = (const float*)d_in[4];
    const float* Wo      = (const float*)d_in[5];

    float* out     = (float*)d_out;                          // [B,S,D]
    float* weights = out + (long long)BB * SS * DD;          // [B,S,S]

    __half *xh, *ch, *wth, *qh, *kh, *vth, *wh, *ctxh;
    cudaGetSymbolAddress((void**)&xh,   g_XH);
    cudaGetSymbolAddress((void**)&ch,   g_CH);
    cudaGetSymbolAddress((void**)&wth,  g_WTH);
    cudaGetSymbolAddress((void**)&qh,   g_QH);
    cudaGetSymbolAddress((void**)&kh,   g_KH);
    cudaGetSymbolAddress((void**)&vth,  g_VTH);
    cudaGetSymbolAddress((void**)&wh,   g_WH);
    cudaGetSymbolAddress((void**)&ctxh, g_CTXH);
    __half* WqT = wth;
    __half* WkT = wth + 1 * DD * DD;
    __half* WvT = wth + 2 * DD * DD;
    __half* WoT = wth + 3 * DD * DD;

    cudaFuncSetAttribute(gemm_nt_f16,
                         cudaFuncAttributeMaxDynamicSharedMemorySize, SM_TOTAL);

    const dim3 blk(256);
    const dim3 tblk(32, 8);
    const long long SD  = (long long)SS * DD;
    const long long SSq = (long long)SS * SS;
    const long long NX  = (long long)BB * SS * DD;

    // 0) Fused prologue: dual cvt (1 launch) + batched weight transpose (1 launch)
    cvt2_f32_f16<<<(unsigned)((NX / 4 + 255) / 256), blk>>>(input, xh, context, ch, NX);
    {
        dim3 g(DD / 32, DD / 32, 4);
        transpose4_f32_to_f16<<<g, tblk>>>(Wq, Wk, Wv, Wo, wth);
    }

    // 1) Projections: Q,K fp16; V written TRANSPOSED directly (mode 2)
    {
        dim3 g(DD / BN, (BB * SS) / BM, 1);
        gemm_nt_f16<<<g, blk, SM_TOTAL>>>(xh, WqT, qh,  DD, DD, 0, 0, 0, 1.0f, 1);
        gemm_nt_f16<<<g, blk, SM_TOTAL>>>(ch, WkT, kh,  DD, DD, 0, 0, 0, 1.0f, 1);
        gemm_nt_f16<<<g, blk, SM_TOTAL>>>(ch, WvT, vth, DD, DD, 0, 0, 0, 1.0f, 2);
    }

    // 2) scores = Q @ K^T * (1/sqrt(D)) -> weights slice (fp32 out)
    {
        dim3 g(SS / BN, SS / BM, BB);
        gemm_nt_f16<<<g, blk, SM_TOTAL>>>(qh, kh, weights, DD, SS, SD, SD, SSq, 0.03125f, 0);
    }

    // 3) softmax in place (fp32) + fp16 copy
    softmax_rows<<<BB * SS, blk>>>(weights, wh);

    // 4) ctx = weights @ V == NT with V^T rows (fp16 out)
    {
        dim3 g(DD / BN, SS / BM, BB);
        gemm_nt_f16<<<g, blk, SM_TOTAL>>>(wh, vth, ctxh, SS, DD, SSq, SD, SD, 1.0f, 1);
    }

    // 5) output = ctx @ Wo == NT with Wo^T (fp32 out)
    {
        dim3 g(DD / BN, (BB * SS) / BM, 1);
        gemm_nt_f16<<<g, blk, SM_TOTAL>>>(ctxh, WoT, out, DD, DD, 0, 0, 0, 1.0f, 0);
    }
}

// round 13
// speedup vs baseline: 1.1837x; 1.0289x over previous
#include <cuda_runtime.h>
#include <cuda_fp16.h>
#include <math.h>
#include <stdint.h>

// Problem constants
#define BB 8
#define SS 2048
#define DD 1024

// Tiles (fp16): one SW128 row = 128 bytes = 64 fp16 K-elements
#define BM 128
#define BN 256
#define BK 64

// tcgen05 only exists in the arch-specific (sm_103a) compilation pass.
#if defined(__CUDA_ARCH_FEAT_SM103_ALL) || defined(__CUDA_ARCH_FEAT_SM100_ALL) || \
    (defined(__CUDA_ARCH_SPECIFIC__) && (__CUDA_ARCH__ >= 1000))
#define HAS_TCGEN05 1
#else
#define HAS_TCGEN05 0
#endif

// Scratch (allocation-free rule: __device__ globals), all fp16 operands
__device__ __half g_XH[BB * SS * DD];         // input fp16
__device__ __half g_CH[BB * SS * DD];         // context fp16
__device__ __half g_WTH[4][DD * DD];          // WqT,WkT,WvT,WoT fp16
__device__ __half g_QH[BB * SS * DD];
__device__ __half g_KH[BB * SS * DD];
__device__ __half g_VTH[BB * SS * DD];        // V^T per batch [B, D, S] (written by V GEMM)
__device__ __half g_WH[(long long)BB * SS * SS];  // softmax weights fp16 copy
__device__ __half g_CTXH[BB * SS * DD];

// ---------------------------------------------------------------------------
// PTX helpers
// ---------------------------------------------------------------------------
__device__ __forceinline__ uint32_t smem_u32(const void* p) {
    uint32_t a;
    asm("{ .reg .u64 t; cvta.to.shared.u64 t, %1; cvt.u32.u64 %0, t; }" : "=r"(a) : "l"(p));
    return a;
}

#if HAS_TCGEN05
__device__ __forceinline__ uint32_t elect_one() {
    uint32_t pred;
    asm volatile("{\n\t.reg .pred p;\n\telect.sync _|p, 0xFFFFFFFF;\n\tselp.b32 %0, 1, 0, p;\n\t}" : "=r"(pred));
    return pred;
}
#define MBAR_INIT(addr, cnt) \
    asm volatile("mbarrier.init.shared.b64 [%0], %1;" :: "r"(addr), "r"(cnt) : "memory")
#define MBAR_WAIT(addr, par) do {                                              \
    uint32_t _m = (addr), _p = (par), _d;                                      \
    asm volatile("{\n\t.reg .pred p;\n\t"                                      \
        "mbarrier.try_wait.parity.acquire.cta.shared::cta.b64 p, [%1], %2;\n\t"\
        "selp.b32 %0, 1, 0, p;\n\t}" : "=r"(_d) : "r"(_m), "r"(_p) : "memory");\
    if (!_d) {                                                                 \
        asm volatile("{\n\t.reg .pred P1;\n\t"                                 \
        "W_%=:\n\t"                                                            \
        "mbarrier.try_wait.parity.acquire.cta.shared::cta.b64 P1, [%0], %1, 0x989680;\n\t" \
        "@P1 bra.uni D_%=;\n\tbra.uni W_%=;\n\tD_%=:\n\t}"                     \
        :: "r"(_m), "r"(_p) : "memory");                                       \
    }                                                                          \
} while (0)

#define TCG_ALLOC(smem_addr, n) \
    asm volatile("tcgen05.alloc.cta_group::1.sync.aligned.shared::cta.b32 [%0], %1;" :: "r"(smem_addr), "r"(n) : "memory")
#define TCG_RELINQ() \
    asm volatile("tcgen05.relinquish_alloc_permit.cta_group::1.sync.aligned;")
#define TCG_DEALLOC(tmem, n) \
    asm volatile("tcgen05.dealloc.cta_group::1.sync.aligned.b32 %0, %1;" :: "r"(tmem), "r"(n))
#define TCG_COMMIT(mbar) \
    asm volatile("tcgen05.commit.cta_group::1.mbarrier::arrive::one.shared::cluster.b64 [%0];" :: "r"(mbar) : "memory")
#define TCG_FENCE_BEFORE() asm volatile("tcgen05.fence::before_thread_sync;" ::: "memory")
#define TCG_FENCE_AFTER()  asm volatile("tcgen05.fence::after_thread_sync;" ::: "memory")
#define TCG_WAIT_LD()      asm volatile("tcgen05.wait::ld.sync.aligned;" ::: "memory")
#define FENCE_ASYNC_SHARED() asm volatile("fence.proxy.async.shared::cta;" ::: "memory")

// 16B async copy (LDGSTS): no register staging, cheap issue.
__device__ __forceinline__ void cp16(uint32_t dst, const void* src) {
    asm volatile("cp.async.cg.shared.global [%0], [%1], 16;" :: "r"(dst), "l"(src) : "memory");
}
// mbarrier arrive when all of this thread's prior cp.asyncs have completed.
#define CPA_MBAR_ARRIVE(addr) \
    asm volatile("cp.async.mbarrier.arrive.noinc.shared.b64 [%0];" :: "r"(addr) : "memory")

#define TCG_LD_X32(r, tmem)                                                    \
    asm volatile("tcgen05.ld.sync.aligned.32x32b.x32.b32 "                     \
        "{%0, %1, %2, %3, %4, %5, %6, %7, %8, %9, %10, %11, %12, %13, %14, %15, " \
        " %16, %17, %18, %19, %20, %21, %22, %23, %24, %25, %26, %27, %28, %29, %30, %31}, [%32];" \
        : "=r"((r)[0]),  "=r"((r)[1]),  "=r"((r)[2]),  "=r"((r)[3]),           \
          "=r"((r)[4]),  "=r"((r)[5]),  "=r"((r)[6]),  "=r"((r)[7]),           \
          "=r"((r)[8]),  "=r"((r)[9]),  "=r"((r)[10]), "=r"((r)[11]),          \
          "=r"((r)[12]), "=r"((r)[13]), "=r"((r)[14]), "=r"((r)[15]),          \
          "=r"((r)[16]), "=r"((r)[17]), "=r"((r)[18]), "=r"((r)[19]),          \
          "=r"((r)[20]), "=r"((r)[21]), "=r"((r)[22]), "=r"((r)[23]),          \
          "=r"((r)[24]), "=r"((r)[25]), "=r"((r)[26]), "=r"((r)[27]),          \
          "=r"((r)[28]), "=r"((r)[29]), "=r"((r)[30]), "=r"((r)[31])           \
        : "r"(tmem))

// SW128 K-major SMEM descriptor (layout 2, version 1, LBO=1, SBO=64)
__device__ __forceinline__ uint64_t make_desc(uint32_t addr) {
    const uint64_t base = (uint64_t(2) << 61) | (uint64_t(1) << 46)
                        | (uint64_t(64) << 32) | (uint64_t(1) << 16);
    return base | ((uint64_t)(addr >> 4) & 0x3FFF);
}

// idesc kind::f16, fp16 inputs, fp32 accum
#define IDESC_F16 ((1u << 4) | ((BN / 8) << 17) | ((BM / 16) << 24))

__device__ __forceinline__ void mma_f16_ss(uint32_t d_tmem, uint64_t a_desc,
                                           uint64_t b_desc, uint32_t enable) {
    asm volatile(
        "{\n\t.reg .pred p;\n\t"
        "setp.ne.u32 p, %4, 0;\n\t"
        "tcgen05.mma.cta_group::1.kind::f16 [%0], %1, %2, %3, {%5, %5, %5, %5}, p;\n\t}"
        :: "r"(d_tmem), "l"(a_desc), "l"(b_desc), "r"(IDESC_F16),
           "r"(enable), "r"(0u)
        : "memory");
}
#endif // HAS_TCGEN05

__device__ __forceinline__ uint32_t swz(uint32_t off) {   // SW128 swizzle
    return off ^ ((off >> 3) & 0x70);
}

// SMEM layout (dynamic): [0]=tmem ptr, mbarriers, tiles 1024-aligned
#define SM_TMEMPTR 0
#define SM_FULL0   8
#define SM_FULL1   16
#define SM_DONE0   24
#define SM_DONE1   32
#define SM_A0      1024
#define SM_A1      (SM_A0 + BM * 128)            // A tile = 16KB
#define SM_B0      (SM_A1 + BM * 128)
#define SM_B1      (SM_B0 + BN * 128)            // B tile = 32KB
#define SM_TOTAL   (SM_B1 + BN * 128)            // 99328

// ---------------------------------------------------------------------------
// fp16 NT GEMM on tcgen05:  C[m][n] = alpha * sum_k A[m][k] * B[n][k]
// A: [M,K] fp16 rm (rows by*128), B: [N,K] fp16 rm (rows bx*256).
// outMode: 0 = fp32 C[M,ldc]; 1 = fp16 C[M,ldc];
//          2 = fp16 TRANSPOSED per-batch: C[b][n][s] with mGlobal=b*SS+s.
// K multiple of 64.
// Mainloop: WARP-SPECIALIZED. Warps 0-3 = producers (cp.async +
// cp.async.mbarrier.arrive onto full(buf), backpressure via done(buf)).
// Warp 4 elected thread = consumer (wait full -> fence -> 4 MMAs -> commit
// to done(buf)). No __syncthreads / cp.async.wait_group in the loop.
// ---------------------------------------------------------------------------
__global__ void __launch_bounds__(256)
gemm_nt_f16(const __half* __restrict__ A, const __half* __restrict__ B,
            void* __restrict__ Cv, int K, int ldc,
            long long sA, long long sB, long long sC, float alpha, int outMode)
{
    const int tid = threadIdx.x;

    A += (long long)blockIdx.z * sA + (long long)blockIdx.y * BM * K;
    B += (long long)blockIdx.z * sB + (long long)blockIdx.x * BN * K;
    const long long cOff = (long long)blockIdx.z * sC
                         + (long long)blockIdx.y * BM * ldc
                         + (long long)blockIdx.x * BN;

#if HAS_TCGEN05
    extern __shared__ char smem[];
    const uint32_t sbase = smem_u32(smem);
    const int wid = tid >> 5;
    const int lid = tid & 31;

    if (wid == 0) {
        TCG_ALLOC(sbase + SM_TMEMPTR, 256);
        TCG_RELINQ();
    }
    if (tid == 0) {
        MBAR_INIT(sbase + SM_FULL0, 128);   // one arrive per producer thread
        MBAR_INIT(sbase + SM_FULL1, 128);
        MBAR_INIT(sbase + SM_DONE0, 1);     // tcgen05.commit
        MBAR_INIT(sbase + SM_DONE1, 1);
    }
    __syncthreads();
    uint32_t tmem;
    asm volatile("ld.shared.b32 %0, [%1];" : "=r"(tmem) : "r"(sbase + SM_TMEMPTR));

    const int KT = K / BK;

    if (wid < 4) {
        // ---- Producers: 128 threads; 8 lanes per 128B row, 16 rows/pass ----
        const int prow  = tid >> 3;              // 0..15
        const int pcolB = (tid & 7) * 16;        // byte offset in row
        const int pcolE = (tid & 7) * 8;         // fp16 element offset
        for (int j = 0; j < KT; j++) {
            const int buf = j & 1;
            const int use = j >> 1;
            if (use > 0)
                MBAR_WAIT(sbase + (buf ? SM_DONE1 : SM_DONE0), (use - 1) & 1);
            const uint32_t aBase = sbase + (buf ? SM_A1 : SM_A0);
            const uint32_t bBase = sbase + (buf ? SM_B1 : SM_B0);
            const long long k0 = (long long)j * BK;
            #pragma unroll
            for (int p = 0; p < BM / 16; p++) {  // 8 passes: 128 A rows
                const int r = prow + p * 16;
                cp16(aBase + swz((uint32_t)(r * 128 + pcolB)),
                     A + (long long)r * K + k0 + pcolE);
            }
            #pragma unroll
            for (int p = 0; p < BN / 16; p++) {  // 16 passes: 256 B rows
                const int r = prow + p * 16;
                cp16(bBase + swz((uint32_t)(r * 128 + pcolB)),
                     B + (long long)r * K + k0 + pcolE);
            }
            CPA_MBAR_ARRIVE(sbase + (buf ? SM_FULL1 : SM_FULL0));
        }
    } else if (wid == 4) {
        // ---- Consumer: one elected thread issues all MMAs ----
        if (elect_one()) {
            for (int ic = 0; ic < KT; ic++) {
                const int buf = ic & 1;
                MBAR_WAIT(sbase + (buf ? SM_FULL1 : SM_FULL0), (ic >> 1) & 1);
                FENCE_ASYNC_SHARED();
                const uint32_t aBase = sbase + (buf ? SM_A1 : SM_A0);
                const uint32_t bBase = sbase + (buf ? SM_B1 : SM_B0);
                const uint64_t ad = make_desc(aBase);
                const uint64_t bd = make_desc(bBase);
                #pragma unroll
                for (int s = 0; s < 4; s++) {
                    mma_f16_ss(tmem, ad + s * 2, bd + s * 2,
                               (ic > 0 || s > 0) ? 1u : 0u);
                }
                TCG_COMMIT(sbase + (buf ? SM_DONE1 : SM_DONE0));
            }
            // Wait for the final commit (in-order per CTA => all MMAs done).
            // Only the consumer polls; other warps held by the barrier below.
            const int lastBuf = (KT - 1) & 1;
            const int cnt = (KT + 1) >> 1;
            MBAR_WAIT(sbase + (lastBuf ? SM_DONE1 : SM_DONE0), (cnt - 1) & 1);
        }
    }
    __syncthreads();                 // releases everyone once MMAs are done
    TCG_FENCE_AFTER();

    // Epilogue: 8 warps; rows (wid&3)*32+lid, col half (wid>>2)*128.
    // Paired TMEM loads: issue 2 x LD_X32, wait once, store both.
    {
        const int m = (wid & 3) * 32 + lid;
        const int chalf = (wid >> 2) * 128;
        const long long mG = (long long)blockIdx.y * BM + m;
        const long long b2 = mG >> 11;            // /SS
        const long long s2 = mG & (SS - 1);
        __half* tbase = (__half*)Cv + b2 * ((long long)DD * SS) + s2
                      + (long long)(blockIdx.x * BN + chalf) * SS;
        #pragma unroll
        for (int jp = 0; jp < 2; jp++) {          // 2 pairs of 32-col groups
            uint32_t r0[32], r1[32];
            TCG_LD_X32(r0, tmem + chalf + (jp * 2 + 0) * 32);
            TCG_LD_X32(r1, tmem + chalf + (jp * 2 + 1) * 32);
            TCG_WAIT_LD();
            float f[64];
            #pragma unroll
            for (int c = 0; c < 32; c++) f[c]      = __uint_as_float(r0[c]) * alpha;
            #pragma unroll
            for (int c = 0; c < 32; c++) f[32 + c] = __uint_as_float(r1[c]) * alpha;
            if (outMode == 0) {
                float* crow = (float*)Cv + cOff + (long long)m * ldc + chalf + jp * 64;
                #pragma unroll
                for (int c = 0; c < 16; c++)
                    *reinterpret_cast<float4*>(crow + c * 4) =
                        *reinterpret_cast<float4*>(&f[c * 4]);
            } else if (outMode == 1) {
                __half* crow = (__half*)Cv + cOff + (long long)m * ldc + chalf + jp * 64;
                #pragma unroll
                for (int c = 0; c < 8; c++) {
                    __half2 p0 = __floats2half2_rn(f[c*8+0], f[c*8+1]);
                    __half2 p1 = __floats2half2_rn(f[c*8+2], f[c*8+3]);
                    __half2 p2 = __floats2half2_rn(f[c*8+4], f[c*8+5]);
                    __half2 p3 = __floats2half2_rn(f[c*8+6], f[c*8+7]);
                    uint4 v = make_uint4(*(uint32_t*)&p0, *(uint32_t*)&p1,
                                         *(uint32_t*)&p2, *(uint32_t*)&p3);
                    *reinterpret_cast<uint4*>(crow + c * 8) = v;
                }
            } else {
                // Transposed fp16: element (m, n) -> C[b][n][s].
                #pragma unroll
                for (int c = 0; c < 64; c++)
                    tbase[(long long)(jp * 64 + c) * SS] = __float2half(f[c]);
            }
        }
    }
    TCG_FENCE_BEFORE();
    __syncthreads();
    if (wid == 0) TCG_DEALLOC(tmem, 256);

#else
    // Baseline-pass fallback (never selected at runtime on sm_103a).
    const int trow = (tid >> 4) * 8;
    const int tcol = (tid & 15) * 16;
    float acc[8][16];
    #pragma unroll
    for (int i = 0; i < 8; i++)
        #pragma unroll
        for (int j = 0; j < 16; j++) acc[i][j] = 0.f;
    for (int k = 0; k < K; k++) {
        float ar[8], br[16];
        #pragma unroll
        for (int i = 0; i < 8; i++) ar[i] = __half2float(A[(long long)(trow + i) * K + k]);
        #pragma unroll
        for (int j = 0; j < 16; j++) br[j] = __half2float(B[(long long)(tcol + j) * K + k]);
        #pragma unroll
        for (int i = 0; i < 8; i++)
            #pragma unroll
            for (int j = 0; j < 16; j++)
                acc[i][j] = fmaf(ar[i], br[j], acc[i][j]);
    }
    #pragma unroll
    for (int i = 0; i < 8; i++)
        #pragma unroll
        for (int j = 0; j < 16; j++) {
            const float val = acc[i][j] * alpha;
            if (outMode == 2) {
                const long long mG = (long long)blockIdx.y * BM + trow + i;
                const long long b2 = mG >> 11, s2 = mG & (SS - 1);
                const long long n = blockIdx.x * BN + tcol + j;
                ((__half*)Cv)[b2 * ((long long)DD * SS) + n * SS + s2] = __float2half(val);
            } else {
                const long long idx = cOff + (long long)(trow + i) * ldc + tcol + j;
                if (outMode == 1) ((__half*)Cv)[idx] = __float2half(val);
                else              ((float*)Cv)[idx] = val;
            }
        }
#endif
}

// ---------------------------------------------------------------------------
// Fused dual convert fp32 -> fp16 (input + context in one launch)
// ---------------------------------------------------------------------------
__global__ void __launch_bounds__(256)
cvt2_f32_f16(const float* __restrict__ in0, __half* __restrict__ out0,
             const float* __restrict__ in1, __half* __restrict__ out1,
             long long n)
{
    const long long i = ((long long)blockIdx.x * 256 + threadIdx.x) * 4;
    if (i + 3 < n) {
        float4 v = *reinterpret_cast<const float4*>(in0 + i);
        __half2 a = __floats2half2_rn(v.x, v.y);
        __half2 b = __floats2half2_rn(v.z, v.w);
        *reinterpret_cast<uint2*>(out0 + i) =
            make_uint2(*(uint32_t*)&a, *(uint32_t*)&b);
        float4 w = *reinterpret_cast<const float4*>(in1 + i);
        __half2 c = __floats2half2_rn(w.x, w.y);
        __half2 d = __floats2half2_rn(w.z, w.w);
        *reinterpret_cast<uint2*>(out1 + i) =
            make_uint2(*(uint32_t*)&c, *(uint32_t*)&d);
    }
}

// ---------------------------------------------------------------------------
// Batched transpose fp32 -> fp16: out[z][c][r] = (half) in[z][r][c]
// ---------------------------------------------------------------------------
__global__ void __launch_bounds__(256)
transpose4_f32_to_f16(const float* __restrict__ w0, const float* __restrict__ w1,
                      const float* __restrict__ w2, const float* __restrict__ w3,
                      __half* __restrict__ outBase)
{
    __shared__ float t[32][33];
    const float* in = (blockIdx.z == 0) ? w0 : (blockIdx.z == 1) ? w1
                    : (blockIdx.z == 2) ? w2 : w3;
    __half* out = outBase + (long long)blockIdx.z * DD * DD;
    const int c0 = blockIdx.x * 32, r0 = blockIdx.y * 32;
    #pragma unroll
    for (int i = threadIdx.y; i < 32; i += 8)
        t[i][threadIdx.x] = in[(long long)(r0 + i) * DD + c0 + threadIdx.x];
    __syncthreads();
    #pragma unroll
    for (int i = threadIdx.y; i < 32; i += 8)
        out[(long long)(c0 + i) * DD + r0 + threadIdx.x] = __float2half(t[threadIdx.x][i]);
}

// ---------------------------------------------------------------------------
// Row softmax in place (fp32) + fp16 copy. One block per row, 256 threads.
// Vectorized: thread t owns cols [8t, 8t+8) as 2x float4.
// ---------------------------------------------------------------------------
__inline__ __device__ float warpMax(float v) {
    #pragma unroll
    for (int o = 16; o > 0; o >>= 1) v = fmaxf(v, __shfl_xor_sync(0xffffffffu, v, o));
    return v;
}
__inline__ __device__ float warpSum(float v) {
    #pragma unroll
    for (int o = 16; o > 0; o >>= 1) v += __shfl_xor_sync(0xffffffffu, v, o);
    return v;
}

__global__ void __launch_bounds__(256)
softmax_rows(float* __restrict__ W, __half* __restrict__ WH)
{
    float* row = W + (long long)blockIdx.x * SS;
    __half* hrow = WH + (long long)blockIdx.x * SS;
    const int tid = threadIdx.x;
    const int base = tid * 8;
    __shared__ float red[8];

    float4 v0 = *reinterpret_cast<const float4*>(row + base);
    float4 v1 = *reinterpret_cast<const float4*>(row + base + 4);
    float v[8] = { v0.x, v0.y, v0.z, v0.w, v1.x, v1.y, v1.z, v1.w };

    float m = v[0];
    #pragma unroll
    for (int i = 1; i < 8; i++) m = fmaxf(m, v[i]);
    m = warpMax(m);
    if ((tid & 31) == 0) red[tid >> 5] = m;
    __syncthreads();
    if (tid < 32) {
        float t = (tid < 8) ? red[tid] : -INFINITY;
        t = warpMax(t);
        if (tid == 0) red[0] = t;
    }
    __syncthreads();
    m = red[0];

    float s = 0.f;
    #pragma unroll
    for (int i = 0; i < 8; i++) {
        v[i] = __expf(v[i] - m);
        s += v[i];
    }
    s = warpSum(s);
    __syncthreads();
    if ((tid & 31) == 0) red[tid >> 5] = s;
    __syncthreads();
    if (tid < 32) {
        float t = (tid < 8) ? red[tid] : 0.f;
        t = warpSum(t);
        if (tid == 0) red[0] = t;
    }
    __syncthreads();
    const float inv = 1.0f / red[0];

    #pragma unroll
    for (int i = 0; i < 8; i++) v[i] *= inv;

    *reinterpret_cast<float4*>(row + base)     = make_float4(v[0], v[1], v[2], v[3]);
    *reinterpret_cast<float4*>(row + base + 4) = make_float4(v[4], v[5], v[6], v[7]);
    __half2 h0 = __floats2half2_rn(v[0], v[1]);
    __half2 h1 = __floats2half2_rn(v[2], v[3]);
    __half2 h2 = __floats2half2_rn(v[4], v[5]);
    __half2 h3 = __floats2half2_rn(v[6], v[7]);
    uint4 hv = make_uint4(*(uint32_t*)&h0, *(uint32_t*)&h1,
                          *(uint32_t*)&h2, *(uint32_t*)&h3);
    *reinterpret_cast<uint4*>(hrow + base) = hv;
}

// ---------------------------------------------------------------------------
// kernel_launch
// d_in: 0=input [B,S,D], 1=context [B,S,D], 2=Wq, 3=Wk, 4=Wv, 5=Wo ([D,D])
// d_out: output [B,S,D] then weights [B,S,S], fp32.
// ---------------------------------------------------------------------------
extern "C" void kernel_launch(void* const* d_in, const int* in_sizes, int n_in,
                              void* d_out, int out_size)
{
    const float* input   = (const float*)d_in[0];
    const float* context = (const float*)d_in[1];
    const float* Wq      = (const float*)d_in[2];
    const float* Wk      = (const float*)d_in[3];
    const float* Wv      = (const float*)d_in[4];
    const float* Wo      = (const float*)d_in[5];

    float* out     = (float*)d_out;                          // [B,S,D]
    float* weights = out + (long long)BB * SS * DD;          // [B,S,S]

    __half *xh, *ch, *wth, *qh, *kh, *vth, *wh, *ctxh;
    cudaGetSymbolAddress((void**)&xh,   g_XH);
    cudaGetSymbolAddress((void**)&ch,   g_CH);
    cudaGetSymbolAddress((void**)&wth,  g_WTH);
    cudaGetSymbolAddress((void**)&qh,   g_QH);
    cudaGetSymbolAddress((void**)&kh,   g_KH);
    cudaGetSymbolAddress((void**)&vth,  g_VTH);
    cudaGetSymbolAddress((void**)&wh,   g_WH);
    cudaGetSymbolAddress((void**)&ctxh, g_CTXH);
    __half* WqT = wth;
    __half* WkT = wth + 1 * DD * DD;
    __half* WvT = wth + 2 * DD * DD;
    __half* WoT = wth + 3 * DD * DD;

    cudaFuncSetAttribute(gemm_nt_f16,
                         cudaFuncAttributeMaxDynamicSharedMemorySize, SM_TOTAL);

    const dim3 blk(256);
    const dim3 tblk(32, 8);
    const long long SD  = (long long)SS * DD;
    const long long SSq = (long long)SS * SS;
    const long long NX  = (long long)BB * SS * DD;

    // 0) Fused prologue: dual cvt (1 launch) + batched weight transpose (1 launch)
    cvt2_f32_f16<<<(unsigned)((NX / 4 + 255) / 256), blk>>>(input, xh, context, ch, NX);
    {
        dim3 g(DD / 32, DD / 32, 4);
        transpose4_f32_to_f16<<<g, tblk>>>(Wq, Wk, Wv, Wo, wth);
    }

    // 1) Projections: Q,K fp16; V written TRANSPOSED directly (mode 2)
    {
        dim3 g(DD / BN, (BB * SS) / BM, 1);
        gemm_nt_f16<<<g, blk, SM_TOTAL>>>(xh, WqT, qh,  DD, DD, 0, 0, 0, 1.0f, 1);
        gemm_nt_f16<<<g, blk, SM_TOTAL>>>(ch, WkT, kh,  DD, DD, 0, 0, 0, 1.0f, 1);
        gemm_nt_f16<<<g, blk, SM_TOTAL>>>(ch, WvT, vth, DD, DD, 0, 0, 0, 1.0f, 2);
    }

    // 2) scores = Q @ K^T * (1/sqrt(D)) -> weights slice (fp32 out)
    {
        dim3 g(SS / BN, SS / BM, BB);
        gemm_nt_f16<<<g, blk, SM_TOTAL>>>(qh, kh, weights, DD, SS, SD, SD, SSq, 0.03125f, 0);
    }

    // 3) softmax in place (fp32) + fp16 copy
    softmax_rows<<<BB * SS, blk>>>(weights, wh);

    // 4) ctx = weights @ V == NT with V^T rows (fp16 out)
    {
        dim3 g(DD / BN, SS / BM, BB);
        gemm_nt_f16<<<g, blk, SM_TOTAL>>>(wh, vth, ctxh, SS, DD, SSq, SD, SD, 1.0f, 1);
    }

    // 5) output = ctx @ Wo == NT with Wo^T (fp32 out)
    {
        dim3 g(DD / BN, (BB * SS) / BM, 1);
        gemm_nt_f16<<<g, blk, SM_TOTAL>>>(ctxh, WoT, out, DD, DD, 0, 0, 0, 1.0f, 0);
    }
}